// round 4
// baseline (speedup 1.0000x reference)
#include <cuda_runtime.h>

#define NN 8192
#define CCH 256
#define DDH 128

// scratch (allocation-free: device globals)
__device__ float g_fi[NN*DDH];
__device__ float g_fj[NN*DDH];
__device__ float g_fk[NN*DDH];
__device__ float g_t [NN*DDH];

#define FMA4(A, S, F) do { (A).x += (S)*(F).x; (A).y += (S)*(F).y; (A).z += (S)*(F).z; (A).w += (S)*(F).w; } while(0)

// ---------------------------------------------------------------------------
// Stage 1: projections  fi/fj/fk = [lm|feat] @ W + b     grid (128,3) x 256
// dynamic smem: s_lm[64*4] + s_x[64*68] + s_W[64*128]
// ---------------------------------------------------------------------------
#define PROJ_SMEM ((64*4 + 64*68 + 64*128) * 4)

__global__ void __launch_bounds__(256)
proj_kernel(const float* __restrict__ lm,
            const float* __restrict__ feat,
            const float* __restrict__ Wi, const float* __restrict__ bi,
            const float* __restrict__ Wj, const float* __restrict__ bj,
            const float* __restrict__ Wk, const float* __restrict__ bk)
{
    extern __shared__ float sm[];
    float* s_lm = sm;                  // [64][4]
    float* s_x  = sm + 64*4;           // [64][68]
    float* s_W  = sm + 64*4 + 64*68;   // [64][128]

    const float* W; const float* b; float* outp;
    if (blockIdx.y == 0)      { W = Wi; b = bi; outp = g_fi; }
    else if (blockIdx.y == 1) { W = Wj; b = bj; outp = g_fj; }
    else                      { W = Wk; b = bk; outp = g_fk; }

    const int tid = threadIdx.x;
    const int tx = tid & 15, ty = tid >> 4;
    const int row0 = blockIdx.x * 64;

    for (int i = tid; i < 64*3; i += 256) {
        int r = i / 3, k = i % 3;
        s_lm[r*4 + k] = lm[(row0 + r)*3 + k];
    }

    // init accumulators with bias; thread owns rows ty+16*rr, cols tx*4+64*h
    float4 acc[4][2];
    #pragma unroll
    for (int h = 0; h < 2; ++h) {
        float4 bv = *(const float4*)(b + tx*4 + 64*h);
        #pragma unroll
        for (int rr = 0; rr < 4; ++rr) acc[rr][h] = bv;
    }

    __syncthreads();

    // landmark columns (k = 0..2)
    #pragma unroll
    for (int k = 0; k < 3; ++k) {
        float4 w0 = *(const float4*)(W + k*DDH + tx*4);
        float4 w1 = *(const float4*)(W + k*DDH + tx*4 + 64);
        #pragma unroll
        for (int rr = 0; rr < 4; ++rr) {
            float x = s_lm[(ty + 16*rr)*4 + k];
            FMA4(acc[rr][0], x, w0);
            FMA4(acc[rr][1], x, w1);
        }
    }

    // feature columns in 4 chunks of 64
    for (int kc = 0; kc < 256; kc += 64) {
        __syncthreads();
        for (int i = tid; i < 64*16; i += 256) {       // x tile: 64 rows x 16 float4
            int r = i >> 4, c4 = i & 15;
            *(float4*)(s_x + r*68 + c4*4) =
                *(const float4*)(feat + (row0 + r)*CCH + kc + c4*4);
        }
        for (int i = tid; i < 64*32; i += 256) {       // W rows kc+3 .. kc+66
            int r = i >> 5, c4 = i & 31;
            *(float4*)(s_W + r*DDH + c4*4) =
                *(const float4*)(W + (kc + 3 + r)*DDH + c4*4);
        }
        __syncthreads();
        #pragma unroll 8
        for (int k = 0; k < 64; ++k) {
            float4 w0 = *(float4*)(s_W + k*DDH + tx*4);
            float4 w1 = *(float4*)(s_W + k*DDH + tx*4 + 64);
            #pragma unroll
            for (int rr = 0; rr < 4; ++rr) {
                float x = s_x[(ty + 16*rr)*68 + k];
                FMA4(acc[rr][0], x, w0);
                FMA4(acc[rr][1], x, w1);
            }
        }
    }

    #pragma unroll
    for (int rr = 0; rr < 4; ++rr) {
        int r = row0 + ty + 16*rr;
        *(float4*)(outp + r*DDH + tx*4)      = acc[rr][0];
        *(float4*)(outp + r*DDH + tx*4 + 64) = acc[rr][1];
    }
}

// ---------------------------------------------------------------------------
// Stage 2: flash-style attention.
//   t_i = (sum_j sigmoid(fi_i . fj_j) fk_j) / (sum_j sigmoid(fi_i . fj_j))
// grid 128 x 256 threads. BM=BN=64, D=128. Never materializes [N,N].
// ---------------------------------------------------------------------------
#define ATTN_SMEM ((3*64*132 + 64*64) * 4)

__global__ void __launch_bounds__(256)
attn_kernel()
{
    extern __shared__ float sm[];
    float* s_fi = sm;                 // [64][132]
    float* s_fj = sm + 64*132;        // [64][132]
    float* s_fk = sm + 2*64*132;      // [64][132]
    float* s_S  = sm + 3*64*132;      // [64][64]

    const int tid = threadIdx.x;
    const int tx = tid & 15, ty = tid >> 4;
    const int row0 = blockIdx.x * 64;

    for (int i = tid; i < 64*32; i += 256) {
        int r = i >> 5, c4 = i & 31;
        *(float4*)(s_fi + r*132 + c4*4) =
            *(const float4*)(g_fi + (row0 + r)*DDH + c4*4);
    }

    float4 acc[4][2];
    #pragma unroll
    for (int rr = 0; rr < 4; ++rr) {
        acc[rr][0] = make_float4(0.f, 0.f, 0.f, 0.f);
        acc[rr][1] = make_float4(0.f, 0.f, 0.f, 0.f);
    }
    float rsum[4] = {0.f, 0.f, 0.f, 0.f};

    __syncthreads();

    for (int jt = 0; jt < NN/64; ++jt) {
        const float* fjg = g_fj + jt*64*DDH;
        const float* fkg = g_fk + jt*64*DDH;
        for (int i = tid; i < 64*32; i += 256) {
            int r = i >> 5, c4 = i & 31;
            *(float4*)(s_fj + r*132 + c4*4) = *(const float4*)(fjg + r*DDH + c4*4);
            *(float4*)(s_fk + r*132 + c4*4) = *(const float4*)(fkg + r*DDH + c4*4);
        }
        __syncthreads();

        // S = fi @ fj^T  (4x4 fragment per thread: rows ty+16rr, cols tx+16jj)
        float s[4][4];
        #pragma unroll
        for (int rr = 0; rr < 4; ++rr)
            #pragma unroll
            for (int jj = 0; jj < 4; ++jj) s[rr][jj] = 0.f;

        #pragma unroll 8
        for (int k = 0; k < DDH; k += 4) {
            float4 a[4], bq[4];
            #pragma unroll
            for (int rr = 0; rr < 4; ++rr) a[rr]  = *(float4*)(s_fi + (ty + 16*rr)*132 + k);
            #pragma unroll
            for (int jj = 0; jj < 4; ++jj) bq[jj] = *(float4*)(s_fj + (tx + 16*jj)*132 + k);
            #pragma unroll
            for (int rr = 0; rr < 4; ++rr)
                #pragma unroll
                for (int jj = 0; jj < 4; ++jj)
                    s[rr][jj] += a[rr].x*bq[jj].x + a[rr].y*bq[jj].y
                               + a[rr].z*bq[jj].z + a[rr].w*bq[jj].w;
        }

        // sigmoid, rowsum accumulate, stash tile for PV
        #pragma unroll
        for (int rr = 0; rr < 4; ++rr)
            #pragma unroll
            for (int jj = 0; jj < 4; ++jj) {
                float v = 1.0f / (1.0f + __expf(-s[rr][jj]));
                rsum[rr] += v;
                s_S[(ty + 16*rr)*64 + tx + 16*jj] = v;
            }
        __syncthreads();

        // acc += S @ fk   (rows ty+16rr, cols tx*4+64h)
        #pragma unroll 4
        for (int j = 0; j < 64; j += 4) {
            float4 sv[4];
            #pragma unroll
            for (int rr = 0; rr < 4; ++rr)
                sv[rr] = *(float4*)(s_S + (ty + 16*rr)*64 + j);
            #pragma unroll
            for (int jl = 0; jl < 4; ++jl) {
                float4 f0 = *(float4*)(s_fk + (j + jl)*132 + tx*4);
                float4 f1 = *(float4*)(s_fk + (j + jl)*132 + tx*4 + 64);
                #pragma unroll
                for (int rr = 0; rr < 4; ++rr) {
                    float sj = ((float*)&sv[rr])[jl];
                    FMA4(acc[rr][0], sj, f0);
                    FMA4(acc[rr][1], sj, f1);
                }
            }
        }
        __syncthreads();
    }

    // reduce rowsums across the 16 lanes sharing each row group (stays in half-warp)
    #pragma unroll
    for (int rr = 0; rr < 4; ++rr) {
        float v = rsum[rr];
        #pragma unroll
        for (int m = 1; m < 16; m <<= 1)
            v += __shfl_xor_sync(0xffffffffu, v, m);
        rsum[rr] = v;
    }

    #pragma unroll
    for (int rr = 0; rr < 4; ++rr) {
        float inv = 1.0f / rsum[rr];
        int r = row0 + ty + 16*rr;
        float4 o0 = acc[rr][0], o1 = acc[rr][1];
        o0.x *= inv; o0.y *= inv; o0.z *= inv; o0.w *= inv;
        o1.x *= inv; o1.y *= inv; o1.z *= inv; o1.w *= inv;
        *(float4*)(g_t + r*DDH + tx*4)      = o0;
        *(float4*)(g_t + r*DDH + tx*4 + 64) = o1;
    }
}

// ---------------------------------------------------------------------------
// Stage 3: out = features + t @ Wr + br    grid 256 x 256 threads (32 rows)
// ---------------------------------------------------------------------------
__global__ void __launch_bounds__(256)
out_kernel(const float* __restrict__ feat,
           const float* __restrict__ Wr,
           const float* __restrict__ br,
           float* __restrict__ out)
{
    __shared__ float s_t[32*132];
    const int tid = threadIdx.x;
    const int tx = tid & 15, ty = tid >> 4;
    const int row0 = blockIdx.x * 32;

    for (int i = tid; i < 32*32; i += 256) {
        int r = i >> 5, c4 = i & 31;
        *(float4*)(s_t + r*132 + c4*4) =
            *(const float4*)(g_t + (row0 + r)*DDH + c4*4);
    }

    float4 acc[2][4];
    #pragma unroll
    for (int rr = 0; rr < 2; ++rr)
        #pragma unroll
        for (int h = 0; h < 4; ++h) acc[rr][h] = make_float4(0.f, 0.f, 0.f, 0.f);

    __syncthreads();

    #pragma unroll 4
    for (int k = 0; k < DDH; ++k) {
        float4 w[4];
        #pragma unroll
        for (int h = 0; h < 4; ++h)
            w[h] = *(const float4*)(Wr + k*CCH + tx*4 + 64*h);
        float t0 = s_t[ty*132 + k];
        float t1 = s_t[(ty + 16)*132 + k];
        #pragma unroll
        for (int h = 0; h < 4; ++h) {
            FMA4(acc[0][h], t0, w[h]);
            FMA4(acc[1][h], t1, w[h]);
        }
    }

    #pragma unroll
    for (int rr = 0; rr < 2; ++rr) {
        int r = row0 + ty + 16*rr;
        #pragma unroll
        for (int h = 0; h < 4; ++h) {
            int c = tx*4 + 64*h;
            float4 bv = *(const float4*)(br + c);
            float4 fv = *(const float4*)(feat + r*CCH + c);
            float4 o  = acc[rr][h];
            o.x += bv.x + fv.x; o.y += bv.y + fv.y;
            o.z += bv.z + fv.z; o.w += bv.w + fv.w;
            *(float4*)(out + r*CCH + c) = o;
        }
    }
}

// ---------------------------------------------------------------------------
extern "C" void kernel_launch(void* const* d_in, const int* in_sizes, int n_in,
                              void* d_out, int out_size)
{
    const float* lm   = (const float*)d_in[0];
    const float* feat = (const float*)d_in[1];
    const float* Wi   = (const float*)d_in[2];
    const float* bi   = (const float*)d_in[3];
    const float* Wj   = (const float*)d_in[4];
    const float* bj   = (const float*)d_in[5];
    const float* Wk   = (const float*)d_in[6];
    const float* bk   = (const float*)d_in[7];
    const float* Wr   = (const float*)d_in[8];
    const float* br   = (const float*)d_in[9];
    float* out = (float*)d_out;

    cudaFuncSetAttribute(proj_kernel, cudaFuncAttributeMaxDynamicSharedMemorySize, PROJ_SMEM);
    cudaFuncSetAttribute(attn_kernel, cudaFuncAttributeMaxDynamicSharedMemorySize, ATTN_SMEM);

    proj_kernel<<<dim3(NN/64, 3), 256, PROJ_SMEM>>>(lm, feat, Wi, bi, Wj, bj, Wk, bk);
    attn_kernel<<<NN/64, 256, ATTN_SMEM>>>();
    out_kernel<<<NN/32, 256>>>(feat, Wr, br, out);
}

// round 7
// speedup vs baseline: 3.3866x; 3.3866x over previous
#include <cuda_runtime.h>
#include <cuda_bf16.h>
#include <cstdint>

#define NN 8192
#define CCH 256
#define DDH 128

// scratch (allocation-free: device globals)
__device__ __nv_bfloat16 g_fib[(size_t)NN*DDH];   // fi bf16, K-major [N][128]
__device__ __nv_bfloat16 g_fjb[(size_t)NN*DDH];   // fj bf16, K-major [N][128]
__device__ __nv_bfloat16 g_fkT[(size_t)DDH*NN];   // fk^T bf16 [128][N]
__device__ float g_t[(size_t)NN*DDH];             // attention output fp32

#define FMA4(A, S, F) do { (A).x += (S)*(F).x; (A).y += (S)*(F).y; (A).z += (S)*(F).z; (A).w += (S)*(F).w; } while(0)

__device__ __forceinline__ float sigf(float x){
    float t, h = 0.5f * x;
    asm("tanh.approx.f32 %0, %1;" : "=f"(t) : "f"(h));
    return fmaf(0.5f, t, 0.5f);
}
__device__ __forceinline__ uint32_t pack_bf2(float lo, float hi){
    __nv_bfloat162 h = __float22bfloat162_rn(make_float2(lo, hi));
    return *(uint32_t*)&h;
}
// D += A(16x16,row) * B(16x8,col), bf16 in, f32 acc  (baseline PTX, sm_80+)
__device__ __forceinline__ void mma16816(float* c, uint32_t a0, uint32_t a1, uint32_t a2, uint32_t a3,
                                         uint32_t b0, uint32_t b1){
    asm volatile("mma.sync.aligned.m16n8k16.row.col.f32.bf16.bf16.f32 "
        "{%0,%1,%2,%3}, {%4,%5,%6,%7}, {%8,%9}, {%0,%1,%2,%3};"
        : "+f"(c[0]), "+f"(c[1]), "+f"(c[2]), "+f"(c[3])
        : "r"(a0), "r"(a1), "r"(a2), "r"(a3), "r"(b0), "r"(b1));
}

// ---------------------------------------------------------------------------
// Stage 1: projections, fp32 math, bf16 outputs (fk transposed via smem stage)
// grid (128,3) x 256
// ---------------------------------------------------------------------------
#define PROJ_SMEM ((64*4 + 64*68 + 64*128) * 4)

__global__ void __launch_bounds__(256)
proj_kernel(const float* __restrict__ lm,
            const float* __restrict__ feat,
            const float* __restrict__ Wi, const float* __restrict__ bi,
            const float* __restrict__ Wj, const float* __restrict__ bj,
            const float* __restrict__ Wk, const float* __restrict__ bk)
{
    extern __shared__ float sm[];
    float* s_lm = sm;                  // [64][4]
    float* s_x  = sm + 64*4;           // [64][68]
    float* s_W  = sm + 64*4 + 64*68;   // [64][128]

    const float* W; const float* b;
    if (blockIdx.y == 0)      { W = Wi; b = bi; }
    else if (blockIdx.y == 1) { W = Wj; b = bj; }
    else                      { W = Wk; b = bk; }

    const int tid = threadIdx.x;
    const int tx = tid & 15, ty = tid >> 4;
    const int row0 = blockIdx.x * 64;

    for (int i = tid; i < 64*3; i += 256) {
        int r = i / 3, k = i % 3;
        s_lm[r*4 + k] = lm[(row0 + r)*3 + k];
    }

    float4 acc[4][2];
    #pragma unroll
    for (int h = 0; h < 2; ++h) {
        float4 bv = *(const float4*)(b + tx*4 + 64*h);
        #pragma unroll
        for (int rr = 0; rr < 4; ++rr) acc[rr][h] = bv;
    }
    __syncthreads();

    #pragma unroll
    for (int k = 0; k < 3; ++k) {
        float4 w0 = *(const float4*)(W + k*DDH + tx*4);
        float4 w1 = *(const float4*)(W + k*DDH + tx*4 + 64);
        #pragma unroll
        for (int rr = 0; rr < 4; ++rr) {
            float x = s_lm[(ty + 16*rr)*4 + k];
            FMA4(acc[rr][0], x, w0);
            FMA4(acc[rr][1], x, w1);
        }
    }

    for (int kc = 0; kc < 256; kc += 64) {
        __syncthreads();
        for (int i = tid; i < 64*16; i += 256) {
            int r = i >> 4, c4 = i & 15;
            *(float4*)(s_x + r*68 + c4*4) =
                *(const float4*)(feat + (row0 + r)*CCH + kc + c4*4);
        }
        for (int i = tid; i < 64*32; i += 256) {
            int r = i >> 5, c4 = i & 31;
            *(float4*)(s_W + r*DDH + c4*4) =
                *(const float4*)(W + (kc + 3 + r)*DDH + c4*4);
        }
        __syncthreads();
        #pragma unroll 8
        for (int k = 0; k < 64; ++k) {
            float4 w0 = *(float4*)(s_W + k*DDH + tx*4);
            float4 w1 = *(float4*)(s_W + k*DDH + tx*4 + 64);
            #pragma unroll
            for (int rr = 0; rr < 4; ++rr) {
                float x = s_x[(ty + 16*rr)*68 + k];
                FMA4(acc[rr][0], x, w0);
                FMA4(acc[rr][1], x, w1);
            }
        }
    }

    if (blockIdx.y < 2) {
        __nv_bfloat16* outb = (blockIdx.y == 0) ? g_fib : g_fjb;
        #pragma unroll
        for (int rr = 0; rr < 4; ++rr) {
            size_t r = row0 + ty + 16*rr;
            #pragma unroll
            for (int h = 0; h < 2; ++h) {
                __nv_bfloat162 p0 = __float22bfloat162_rn(make_float2(acc[rr][h].x, acc[rr][h].y));
                __nv_bfloat162 p1 = __float22bfloat162_rn(make_float2(acc[rr][h].z, acc[rr][h].w));
                uint2 u; u.x = *(uint32_t*)&p0; u.y = *(uint32_t*)&p1;
                *(uint2*)(outb + r*DDH + tx*4 + 64*h) = u;
            }
        }
    } else {
        // stage bf16 tile [64][130] over s_x, then write transposed (coalesced in j)
        __syncthreads();
        __nv_bfloat16* stage = (__nv_bfloat16*)s_x;
        #pragma unroll
        for (int rr = 0; rr < 4; ++rr) {
            int r = ty + 16*rr;
            #pragma unroll
            for (int h = 0; h < 2; ++h) {
                stage[r*130 + tx*4 + 64*h + 0] = __float2bfloat16(acc[rr][h].x);
                stage[r*130 + tx*4 + 64*h + 1] = __float2bfloat16(acc[rr][h].y);
                stage[r*130 + tx*4 + 64*h + 2] = __float2bfloat16(acc[rr][h].z);
                stage[r*130 + tx*4 + 64*h + 3] = __float2bfloat16(acc[rr][h].w);
            }
        }
        __syncthreads();
        for (int i = tid; i < 1024; i += 256) {
            int c = i >> 3, q = i & 7;
            union { __nv_bfloat16 h[8]; uint4 u; } v;
            #pragma unroll
            for (int j = 0; j < 8; ++j) v.h[j] = stage[(q*8 + j)*130 + c];
            *(uint4*)(g_fkT + (size_t)c*NN + row0 + q*8) = v.u;
        }
    }
}

// ---------------------------------------------------------------------------
// Stage 2: flash attention on legacy tensor cores (mma.sync m16n8k16 bf16).
// grid 128 x 128 threads (4 warps). BM=64, BN=64, D=128.
//   S = fi @ fj^T ; P = sigmoid(S) (bf16, via smem) ; acc += P @ fk ; rowsum.
// Warp w owns S/out rows w*16..w*16+15. Lane: g = lane>>2, t = lane&3.
// smem pitches chosen so fragment loads hit banks 4*g + t (conflict-free).
// ---------------------------------------------------------------------------
#define PIT_F 136   // pitch (bf16 elems) for fi/fj tiles  (272B = 68 words -> 4*row spread)
#define PIT_T 72    // pitch for fkT and P tiles           (144B = 36 words -> 4*row spread)
#define OFF_FI 0
#define OFF_FJ (64*PIT_F)
#define OFF_FK (2*64*PIT_F)
#define OFF_P  (2*64*PIT_F + 128*PIT_T)
#define ATTN_SMEM ((2*64*PIT_F + 128*PIT_T + 64*PIT_T) * 2)

__global__ void __launch_bounds__(128)
attn_kernel()
{
    extern __shared__ __nv_bfloat16 sb[];
    __nv_bfloat16* s_fi = sb + OFF_FI;   // [64][136]
    __nv_bfloat16* s_fj = sb + OFF_FJ;   // [64][136]
    __nv_bfloat16* s_fk = sb + OFF_FK;   // [128][72]  (fkT tile: row=d, col=j)
    __nv_bfloat16* s_P  = sb + OFF_P;    // [64][72]

    const int tid  = threadIdx.x;
    const int w    = tid >> 5;
    const int lane = tid & 31;
    const int g    = lane >> 2;
    const int t    = lane & 3;
    const int row0 = blockIdx.x * 64;

    // load fi tile [64][128] -> smem pitch 136
    for (int i = tid; i < 1024; i += 128) {
        int r = i >> 4, c8 = i & 15;
        *(uint4*)(s_fi + r*PIT_F + c8*8) =
            *(const uint4*)(g_fib + (size_t)(row0 + r)*DDH + c8*8);
    }

    float acc[16][4];                       // PV accumulators: 16 d-tiles x 4
    #pragma unroll
    for (int nt = 0; nt < 16; ++nt)
        #pragma unroll
        for (int q = 0; q < 4; ++q) acc[nt][q] = 0.f;
    float rs_lo = 0.f, rs_hi = 0.f;         // rowsum partials (rows w*16+g, +8)

    const int arow = w*16 + g;

    for (int jt = 0; jt < NN/64; ++jt) {
        __syncthreads();   // previous iter's consumers done; smem tiles reusable
        // fj tile [64][128] -> pitch 136 ; fkT tile [128][64] -> pitch 72
        for (int i = tid; i < 1024; i += 128) {
            int r = i >> 4, c8 = i & 15;
            *(uint4*)(s_fj + r*PIT_F + c8*8) =
                *(const uint4*)(g_fjb + (size_t)(jt*64 + r)*DDH + c8*8);
        }
        for (int i = tid; i < 1024; i += 128) {
            int r = i >> 3, c8 = i & 7;
            *(uint4*)(s_fk + r*PIT_T + c8*8) =
                *(const uint4*)(g_fkT + (size_t)r*NN + jt*64 + c8*8);
        }
        __syncthreads();

        // ---- S = fi @ fj^T : warp rows [w*16, w*16+16), cols 0..63 ----
        float sc[8][4];
        #pragma unroll
        for (int nt = 0; nt < 8; ++nt)
            #pragma unroll
            for (int q = 0; q < 4; ++q) sc[nt][q] = 0.f;

        #pragma unroll
        for (int ks = 0; ks < 8; ++ks) {
            const int kc = ks*16 + t*2;
            uint32_t a0 = *(const uint32_t*)(s_fi + arow*PIT_F + kc);
            uint32_t a1 = *(const uint32_t*)(s_fi + (arow + 8)*PIT_F + kc);
            uint32_t a2 = *(const uint32_t*)(s_fi + arow*PIT_F + kc + 8);
            uint32_t a3 = *(const uint32_t*)(s_fi + (arow + 8)*PIT_F + kc + 8);
            #pragma unroll
            for (int nt = 0; nt < 8; ++nt) {
                uint32_t b0 = *(const uint32_t*)(s_fj + (nt*8 + g)*PIT_F + kc);
                uint32_t b1 = *(const uint32_t*)(s_fj + (nt*8 + g)*PIT_F + kc + 8);
                mma16816(sc[nt], a0, a1, a2, a3, b0, b1);
            }
        }

        // ---- sigmoid -> rowsum + P(bf16) in smem ----
        #pragma unroll
        for (int nt = 0; nt < 8; ++nt) {
            float v0 = sigf(sc[nt][0]);
            float v1 = sigf(sc[nt][1]);
            float v2 = sigf(sc[nt][2]);
            float v3 = sigf(sc[nt][3]);
            rs_lo += v0 + v1;
            rs_hi += v2 + v3;
            *(uint32_t*)(s_P + arow*PIT_T + nt*8 + t*2)       = pack_bf2(v0, v1);
            *(uint32_t*)(s_P + (arow + 8)*PIT_T + nt*8 + t*2) = pack_bf2(v2, v3);
        }
        __syncthreads();

        // ---- acc += P @ fk : A = P rows, B = fkT (col-major KxN, ld=PIT_T) ----
        #pragma unroll
        for (int ks = 0; ks < 4; ++ks) {
            const int kc = ks*16 + t*2;
            uint32_t a0 = *(const uint32_t*)(s_P + arow*PIT_T + kc);
            uint32_t a1 = *(const uint32_t*)(s_P + (arow + 8)*PIT_T + kc);
            uint32_t a2 = *(const uint32_t*)(s_P + arow*PIT_T + kc + 8);
            uint32_t a3 = *(const uint32_t*)(s_P + (arow + 8)*PIT_T + kc + 8);
            #pragma unroll
            for (int nt = 0; nt < 16; ++nt) {
                uint32_t b0 = *(const uint32_t*)(s_fk + (nt*8 + g)*PIT_T + kc);
                uint32_t b1 = *(const uint32_t*)(s_fk + (nt*8 + g)*PIT_T + kc + 8);
                mma16816(acc[nt], a0, a1, a2, a3, b0, b1);
            }
        }
    }

    // reduce rowsums across the 4 lanes sharing each row (t = lane&3)
    rs_lo += __shfl_xor_sync(0xffffffffu, rs_lo, 1);
    rs_lo += __shfl_xor_sync(0xffffffffu, rs_lo, 2);
    rs_hi += __shfl_xor_sync(0xffffffffu, rs_hi, 1);
    rs_hi += __shfl_xor_sync(0xffffffffu, rs_hi, 2);
    const float inv_lo = 1.0f / rs_lo;
    const float inv_hi = 1.0f / rs_hi;

    float* o0 = g_t + (size_t)(row0 + arow)*DDH;
    float* o1 = g_t + (size_t)(row0 + arow + 8)*DDH;
    #pragma unroll
    for (int nt = 0; nt < 16; ++nt) {
        int c = nt*8 + t*2;
        *(float2*)(o0 + c) = make_float2(acc[nt][0]*inv_lo, acc[nt][1]*inv_lo);
        *(float2*)(o1 + c) = make_float2(acc[nt][2]*inv_hi, acc[nt][3]*inv_hi);
    }
}

// ---------------------------------------------------------------------------
// Stage 3: out = features + t @ Wr + br    grid 256 x 256 threads
// ---------------------------------------------------------------------------
__global__ void __launch_bounds__(256)
out_kernel(const float* __restrict__ feat,
           const float* __restrict__ Wr,
           const float* __restrict__ br,
           float* __restrict__ out)
{
    __shared__ float s_t[32*132];
    const int tid = threadIdx.x;
    const int tx = tid & 15, ty = tid >> 4;
    const int row0 = blockIdx.x * 32;

    for (int i = tid; i < 32*32; i += 256) {
        int r = i >> 5, c4 = i & 31;
        *(float4*)(s_t + r*132 + c4*4) =
            *(const float4*)(g_t + (size_t)(row0 + r)*DDH + c4*4);
    }

    float4 acc[2][4];
    #pragma unroll
    for (int rr = 0; rr < 2; ++rr)
        #pragma unroll
        for (int h = 0; h < 4; ++h) acc[rr][h] = make_float4(0.f, 0.f, 0.f, 0.f);

    __syncthreads();

    #pragma unroll 4
    for (int k = 0; k < DDH; ++k) {
        float4 w[4];
        #pragma unroll
        for (int h = 0; h < 4; ++h)
            w[h] = *(const float4*)(Wr + k*CCH + tx*4 + 64*h);
        float t0 = s_t[ty*132 + k];
        float t1 = s_t[(ty + 16)*132 + k];
        #pragma unroll
        for (int h = 0; h < 4; ++h) {
            FMA4(acc[0][h], t0, w[h]);
            FMA4(acc[1][h], t1, w[h]);
        }
    }

    #pragma unroll
    for (int rr = 0; rr < 2; ++rr) {
        int r = row0 + ty + 16*rr;
        #pragma unroll
        for (int h = 0; h < 4; ++h) {
            int c = tx*4 + 64*h;
            float4 bv = *(const float4*)(br + c);
            float4 fv = *(const float4*)(feat + (size_t)r*CCH + c);
            float4 o  = acc[rr][h];
            o.x += bv.x + fv.x; o.y += bv.y + fv.y;
            o.z += bv.z + fv.z; o.w += bv.w + fv.w;
            *(float4*)(out + (size_t)r*CCH + c) = o;
        }
    }
}

// ---------------------------------------------------------------------------
extern "C" void kernel_launch(void* const* d_in, const int* in_sizes, int n_in,
                              void* d_out, int out_size)
{
    const float* lm   = (const float*)d_in[0];
    const float* feat = (const float*)d_in[1];
    const float* Wi   = (const float*)d_in[2];
    const float* bi   = (const float*)d_in[3];
    const float* Wj   = (const float*)d_in[4];
    const float* bj   = (const float*)d_in[5];
    const float* Wk   = (const float*)d_in[6];
    const float* bk   = (const float*)d_in[7];
    const float* Wr   = (const float*)d_in[8];
    const float* br   = (const float*)d_in[9];
    float* out = (float*)d_out;

    cudaFuncSetAttribute(proj_kernel, cudaFuncAttributeMaxDynamicSharedMemorySize, PROJ_SMEM);
    cudaFuncSetAttribute(attn_kernel, cudaFuncAttributeMaxDynamicSharedMemorySize, ATTN_SMEM);

    proj_kernel<<<dim3(NN/64, 3), 256, PROJ_SMEM>>>(lm, feat, Wi, bi, Wj, bj, Wk, bk);
    attn_kernel<<<NN/64, 128, ATTN_SMEM>>>();
    out_kernel<<<NN/32, 256>>>(feat, Wr, br, out);
}

// round 8
// speedup vs baseline: 5.3488x; 1.5794x over previous
#include <cuda_runtime.h>
#include <cuda_bf16.h>
#include <cstdint>

#define NN 8192
#define CCH 256
#define DDH 128

// scratch (allocation-free: device globals)
__device__ __nv_bfloat16 g_fib[(size_t)NN*DDH];   // fi bf16, K-major [N][128]
__device__ __nv_bfloat16 g_fjb[(size_t)NN*DDH];   // fj bf16, K-major [N][128]
__device__ __nv_bfloat16 g_fkT[(size_t)DDH*NN];   // fk^T bf16 [128][N]
__device__ float g_t[(size_t)NN*DDH];             // attention output fp32

#define FMA4(A, S, F) do { (A).x += (S)*(F).x; (A).y += (S)*(F).y; (A).z += (S)*(F).z; (A).w += (S)*(F).w; } while(0)

__device__ __forceinline__ float sigf(float x){
    float t, h = 0.5f * x;
    asm("tanh.approx.f32 %0, %1;" : "=f"(t) : "f"(h));
    return fmaf(0.5f, t, 0.5f);
}
__device__ __forceinline__ uint32_t pack_bf2(float lo, float hi){
    __nv_bfloat162 h = __float22bfloat162_rn(make_float2(lo, hi));
    return *(uint32_t*)&h;
}
// D += A(16x16,row) * B(16x8,col), bf16 in, f32 acc  (baseline PTX, sm_80+)
__device__ __forceinline__ void mma16816(float* c, uint32_t a0, uint32_t a1, uint32_t a2, uint32_t a3,
                                         uint32_t b0, uint32_t b1){
    asm volatile("mma.sync.aligned.m16n8k16.row.col.f32.bf16.bf16.f32 "
        "{%0,%1,%2,%3}, {%4,%5,%6,%7}, {%8,%9}, {%0,%1,%2,%3};"
        : "+f"(c[0]), "+f"(c[1]), "+f"(c[2]), "+f"(c[3])
        : "r"(a0), "r"(a1), "r"(a2), "r"(a3), "r"(b0), "r"(b1));
}
__device__ __forceinline__ uint32_t smem_u32(const void* p){
    uint32_t a;
    asm("{ .reg .u64 t; cvta.to.shared.u64 t, %1; cvt.u32.u64 %0, t; }" : "=r"(a) : "l"(p));
    return a;
}
__device__ __forceinline__ void cpa16(uint32_t dst, const void* src){
    asm volatile("cp.async.cg.shared.global [%0], [%1], 16;" :: "r"(dst), "l"(src));
}
#define CPA_COMMIT() asm volatile("cp.async.commit_group;" ::: "memory")
#define CPA_WAIT0()  asm volatile("cp.async.wait_group 0;" ::: "memory")

// ---------------------------------------------------------------------------
// Stage 1: projections, fp32 math, bf16 outputs (fk transposed via smem stage)
// grid (128,3) x 256
// ---------------------------------------------------------------------------
#define PROJ_SMEM ((64*4 + 64*68 + 64*128) * 4)

__global__ void __launch_bounds__(256)
proj_kernel(const float* __restrict__ lm,
            const float* __restrict__ feat,
            const float* __restrict__ Wi, const float* __restrict__ bi,
            const float* __restrict__ Wj, const float* __restrict__ bj,
            const float* __restrict__ Wk, const float* __restrict__ bk)
{
    extern __shared__ float sm[];
    float* s_lm = sm;                  // [64][4]
    float* s_x  = sm + 64*4;           // [64][68]
    float* s_W  = sm + 64*4 + 64*68;   // [64][128]

    const float* W; const float* b;
    if (blockIdx.y == 0)      { W = Wi; b = bi; }
    else if (blockIdx.y == 1) { W = Wj; b = bj; }
    else                      { W = Wk; b = bk; }

    const int tid = threadIdx.x;
    const int tx = tid & 15, ty = tid >> 4;
    const int row0 = blockIdx.x * 64;

    for (int i = tid; i < 64*3; i += 256) {
        int r = i / 3, k = i % 3;
        s_lm[r*4 + k] = lm[(row0 + r)*3 + k];
    }

    float4 acc[4][2];
    #pragma unroll
    for (int h = 0; h < 2; ++h) {
        float4 bv = *(const float4*)(b + tx*4 + 64*h);
        #pragma unroll
        for (int rr = 0; rr < 4; ++rr) acc[rr][h] = bv;
    }
    __syncthreads();

    #pragma unroll
    for (int k = 0; k < 3; ++k) {
        float4 w0 = *(const float4*)(W + k*DDH + tx*4);
        float4 w1 = *(const float4*)(W + k*DDH + tx*4 + 64);
        #pragma unroll
        for (int rr = 0; rr < 4; ++rr) {
            float x = s_lm[(ty + 16*rr)*4 + k];
            FMA4(acc[rr][0], x, w0);
            FMA4(acc[rr][1], x, w1);
        }
    }

    for (int kc = 0; kc < 256; kc += 64) {
        __syncthreads();
        for (int i = tid; i < 64*16; i += 256) {
            int r = i >> 4, c4 = i & 15;
            *(float4*)(s_x + r*68 + c4*4) =
                *(const float4*)(feat + (row0 + r)*CCH + kc + c4*4);
        }
        for (int i = tid; i < 64*32; i += 256) {
            int r = i >> 5, c4 = i & 31;
            *(float4*)(s_W + r*DDH + c4*4) =
                *(const float4*)(W + (kc + 3 + r)*DDH + c4*4);
        }
        __syncthreads();
        #pragma unroll 8
        for (int k = 0; k < 64; ++k) {
            float4 w0 = *(float4*)(s_W + k*DDH + tx*4);
            float4 w1 = *(float4*)(s_W + k*DDH + tx*4 + 64);
            #pragma unroll
            for (int rr = 0; rr < 4; ++rr) {
                float x = s_x[(ty + 16*rr)*68 + k];
                FMA4(acc[rr][0], x, w0);
                FMA4(acc[rr][1], x, w1);
            }
        }
    }

    if (blockIdx.y < 2) {
        __nv_bfloat16* outb = (blockIdx.y == 0) ? g_fib : g_fjb;
        #pragma unroll
        for (int rr = 0; rr < 4; ++rr) {
            size_t r = row0 + ty + 16*rr;
            #pragma unroll
            for (int h = 0; h < 2; ++h) {
                __nv_bfloat162 p0 = __float22bfloat162_rn(make_float2(acc[rr][h].x, acc[rr][h].y));
                __nv_bfloat162 p1 = __float22bfloat162_rn(make_float2(acc[rr][h].z, acc[rr][h].w));
                uint2 u; u.x = *(uint32_t*)&p0; u.y = *(uint32_t*)&p1;
                *(uint2*)(outb + r*DDH + tx*4 + 64*h) = u;
            }
        }
    } else {
        // stage bf16 tile [64][130] over s_x, then write transposed (coalesced in j)
        __syncthreads();
        __nv_bfloat16* stage = (__nv_bfloat16*)s_x;
        #pragma unroll
        for (int rr = 0; rr < 4; ++rr) {
            int r = ty + 16*rr;
            #pragma unroll
            for (int h = 0; h < 2; ++h) {
                stage[r*130 + tx*4 + 64*h + 0] = __float2bfloat16(acc[rr][h].x);
                stage[r*130 + tx*4 + 64*h + 1] = __float2bfloat16(acc[rr][h].y);
                stage[r*130 + tx*4 + 64*h + 2] = __float2bfloat16(acc[rr][h].z);
                stage[r*130 + tx*4 + 64*h + 3] = __float2bfloat16(acc[rr][h].w);
            }
        }
        __syncthreads();
        for (int i = tid; i < 1024; i += 256) {
            int c = i >> 3, q = i & 7;
            union { __nv_bfloat16 h[8]; uint4 u; } v;
            #pragma unroll
            for (int j = 0; j < 8; ++j) v.h[j] = stage[(q*8 + j)*130 + c];
            *(uint4*)(g_fkT + (size_t)c*NN + row0 + q*8) = v.u;
        }
    }
}

// ---------------------------------------------------------------------------
// Stage 2: flash attention, mma.sync m16n8k16 bf16, register-resident P.
// grid 128 x 256 threads (8 warps = 4 row-groups x 2 col-groups).
// BM=64 rows, BN=128 j per iteration, 64 iterations, cp.async double buffer.
//   warp (wr,wc): S rows wr*16..+16, j-cols wc*64..+64 -> sigmoid in regs ->
//   PV partial over its j-half for ALL 128 d-cols; cross-wc reduce at end.
// ---------------------------------------------------------------------------
#define PIT 136   // bf16 pitch: 272B/row = 68 words, 68 mod 32 = 4 -> banks 4g+t
#define OFF_FI 0
#define OFF_FJ (64*PIT)
#define OFF_FK (64*PIT + 2*128*PIT)
#define ATTN_SMEM ((64*PIT + 4*128*PIT) * 2)

__device__ __forceinline__ void load_tile_async(uint32_t fj_u, uint32_t fk_u, int jt, int tid){
    const __nv_bfloat16* fj = g_fjb + (size_t)jt*128*DDH;
    #pragma unroll
    for (int s = 0; s < 8; ++s) {
        int i = tid + s*256;
        int r = i >> 4, c8 = i & 15;
        cpa16(fj_u + (uint32_t)(r*PIT + c8*8)*2, fj + r*DDH + c8*8);
    }
    #pragma unroll
    for (int s = 0; s < 8; ++s) {
        int i = tid + s*256;
        int r = i >> 4, c8 = i & 15;          // r = d, c8*8 = j offset
        cpa16(fk_u + (uint32_t)(r*PIT + c8*8)*2, g_fkT + (size_t)r*NN + jt*128 + c8*8);
    }
}

__global__ void __launch_bounds__(256)
attn_kernel()
{
    extern __shared__ __nv_bfloat16 sb[];
    const int tid  = threadIdx.x;
    const int w    = tid >> 5;
    const int lane = tid & 31;
    const int wr   = w >> 1, wc = w & 1;
    const int g    = lane >> 2, t = lane & 3;
    const int row0 = blockIdx.x * 64;
    const int arow = wr*16 + g;

    __nv_bfloat16* s_fi = sb + OFF_FI;
    const uint32_t sbu = smem_u32(sb);
    const uint32_t fj_u0 = sbu + OFF_FJ*2, fj_u1 = sbu + (OFF_FJ + 128*PIT)*2;
    const uint32_t fk_u0 = sbu + OFF_FK*2, fk_u1 = sbu + (OFF_FK + 128*PIT)*2;

    // fi tile [64][128] (plain loads)
    for (int i = tid; i < 1024; i += 256) {
        int r = i >> 4, c8 = i & 15;
        *(uint4*)(s_fi + r*PIT + c8*8) =
            *(const uint4*)(g_fib + (size_t)(row0 + r)*DDH + c8*8);
    }
    // prefetch tile 0
    load_tile_async(fj_u0, fk_u0, 0, tid);
    CPA_COMMIT();

    float acc[16][4];
    #pragma unroll
    for (int nt = 0; nt < 16; ++nt)
        #pragma unroll
        for (int q = 0; q < 4; ++q) acc[nt][q] = 0.f;
    float rs_lo = 0.f, rs_hi = 0.f;

    for (int jt = 0; jt < NN/128; ++jt) {
        const int buf = jt & 1;
        CPA_WAIT0();
        __syncthreads();                       // tile jt visible; prev compute done
        if (jt + 1 < NN/128) {
            load_tile_async(buf ? fj_u0 : fj_u1, buf ? fk_u0 : fk_u1, jt + 1, tid);
            CPA_COMMIT();
        }
        __nv_bfloat16* s_fj = sb + OFF_FJ + buf*128*PIT;
        __nv_bfloat16* s_fk = sb + OFF_FK + buf*128*PIT;

        // ---- S = fi @ fj^T : rows wr*16..+16, j-cols wc*64..+64 ----
        float sc[8][4];
        #pragma unroll
        for (int nt = 0; nt < 8; ++nt)
            #pragma unroll
            for (int q = 0; q < 4; ++q) sc[nt][q] = 0.f;

        #pragma unroll
        for (int ks = 0; ks < 8; ++ks) {
            const int kc = ks*16 + t*2;
            uint32_t a0 = *(const uint32_t*)(s_fi + arow*PIT + kc);
            uint32_t a1 = *(const uint32_t*)(s_fi + (arow + 8)*PIT + kc);
            uint32_t a2 = *(const uint32_t*)(s_fi + arow*PIT + kc + 8);
            uint32_t a3 = *(const uint32_t*)(s_fi + (arow + 8)*PIT + kc + 8);
            #pragma unroll
            for (int nt = 0; nt < 8; ++nt) {
                const int jrow = wc*64 + nt*8 + g;
                uint32_t b0 = *(const uint32_t*)(s_fj + jrow*PIT + kc);
                uint32_t b1 = *(const uint32_t*)(s_fj + jrow*PIT + kc + 8);
                mma16816(sc[nt], a0, a1, a2, a3, b0, b1);
            }
        }

        // ---- sigmoid in regs -> rowsum + PV A-fragments (no smem) ----
        // S C-frag of n-tiles {2k,2k+1} == PV A-frag of k-tile k (FA2 layout match)
        uint32_t pa[4][4];
        #pragma unroll
        for (int nt = 0; nt < 8; ++nt) {
            float v0 = sigf(sc[nt][0]);
            float v1 = sigf(sc[nt][1]);
            float v2 = sigf(sc[nt][2]);
            float v3 = sigf(sc[nt][3]);
            rs_lo += v0 + v1;
            rs_hi += v2 + v3;
            const int k2 = nt >> 1;
            if (nt & 1) { pa[k2][2] = pack_bf2(v0, v1); pa[k2][3] = pack_bf2(v2, v3); }
            else        { pa[k2][0] = pack_bf2(v0, v1); pa[k2][1] = pack_bf2(v2, v3); }
        }

        // ---- acc += P @ fk over this warp's j-half, all 128 d-cols ----
        #pragma unroll
        for (int ks = 0; ks < 4; ++ks) {
            const int kc = wc*64 + ks*16 + t*2;
            #pragma unroll
            for (int nt = 0; nt < 16; ++nt) {
                const int drow = nt*8 + g;
                uint32_t b0 = *(const uint32_t*)(s_fk + drow*PIT + kc);
                uint32_t b1 = *(const uint32_t*)(s_fk + drow*PIT + kc + 8);
                mma16816(acc[nt], pa[ks][0], pa[ks][1], pa[ks][2], pa[ks][3], b0, b1);
            }
        }
    }

    // rowsum: reduce over the 4 t-lanes sharing each row
    rs_lo += __shfl_xor_sync(0xffffffffu, rs_lo, 1);
    rs_lo += __shfl_xor_sync(0xffffffffu, rs_lo, 2);
    rs_hi += __shfl_xor_sync(0xffffffffu, rs_hi, 1);
    rs_hi += __shfl_xor_sync(0xffffffffu, rs_hi, 2);

    // cross-wc reduction of acc + rowsum (reuse tile smem)
    float* s_red = (float*)(sb + OFF_FJ);     // [64][130] fp32 = 33.3 KB
    float* s_rs  = (float*)(sb + OFF_FK);     // [2][64]
    __syncthreads();
    if (t == 0) {
        s_rs[wc*64 + arow]     = rs_lo;
        s_rs[wc*64 + arow + 8] = rs_hi;
    }
    if (wc == 0) {
        #pragma unroll
        for (int nt = 0; nt < 16; ++nt) {
            *(float2*)(s_red + arow*130 + nt*8 + t*2)       = make_float2(acc[nt][0], acc[nt][1]);
            *(float2*)(s_red + (arow + 8)*130 + nt*8 + t*2) = make_float2(acc[nt][2], acc[nt][3]);
        }
    }
    __syncthreads();
    if (wc == 1) {
        const float inv_lo = 1.0f / (s_rs[arow]     + rs_lo);
        const float inv_hi = 1.0f / (s_rs[arow + 8] + rs_hi);
        float* o0 = g_t + (size_t)(row0 + arow)*DDH;
        float* o1 = g_t + (size_t)(row0 + arow + 8)*DDH;
        #pragma unroll
        for (int nt = 0; nt < 16; ++nt) {
            const int c = nt*8 + t*2;
            float2 p0 = *(float2*)(s_red + arow*130 + c);
            float2 p1 = *(float2*)(s_red + (arow + 8)*130 + c);
            *(float2*)(o0 + c) = make_float2((acc[nt][0] + p0.x)*inv_lo, (acc[nt][1] + p0.y)*inv_lo);
            *(float2*)(o1 + c) = make_float2((acc[nt][2] + p1.x)*inv_hi, (acc[nt][3] + p1.y)*inv_hi);
        }
    }
}

// ---------------------------------------------------------------------------
// Stage 3: out = features + t @ Wr + br    grid 256 x 256 threads
// ---------------------------------------------------------------------------
__global__ void __launch_bounds__(256)
out_kernel(const float* __restrict__ feat,
           const float* __restrict__ Wr,
           const float* __restrict__ br,
           float* __restrict__ out)
{
    __shared__ float s_t[32*132];
    const int tid = threadIdx.x;
    const int tx = tid & 15, ty = tid >> 4;
    const int row0 = blockIdx.x * 32;

    for (int i = tid; i < 32*32; i += 256) {
        int r = i >> 5, c4 = i & 31;
        *(float4*)(s_t + r*132 + c4*4) =
            *(const float4*)(g_t + (size_t)(row0 + r)*DDH + c4*4);
    }

    float4 acc[2][4];
    #pragma unroll
    for (int rr = 0; rr < 2; ++rr)
        #pragma unroll
        for (int h = 0; h < 4; ++h) acc[rr][h] = make_float4(0.f, 0.f, 0.f, 0.f);

    __syncthreads();

    #pragma unroll 4
    for (int k = 0; k < DDH; ++k) {
        float4 w[4];
        #pragma unroll
        for (int h = 0; h < 4; ++h)
            w[h] = *(const float4*)(Wr + k*CCH + tx*4 + 64*h);
        float t0 = s_t[ty*132 + k];
        float t1 = s_t[(ty + 16)*132 + k];
        #pragma unroll
        for (int h = 0; h < 4; ++h) {
            FMA4(acc[0][h], t0, w[h]);
            FMA4(acc[1][h], t1, w[h]);
        }
    }

    #pragma unroll
    for (int rr = 0; rr < 2; ++rr) {
        int r = row0 + ty + 16*rr;
        #pragma unroll
        for (int h = 0; h < 4; ++h) {
            int c = tx*4 + 64*h;
            float4 bv = *(const float4*)(br + c);
            float4 fv = *(const float4*)(feat + (size_t)r*CCH + c);
            float4 o  = acc[rr][h];
            o.x += bv.x + fv.x; o.y += bv.y + fv.y;
            o.z += bv.z + fv.z; o.w += bv.w + fv.w;
            *(float4*)(out + (size_t)r*CCH + c) = o;
        }
    }
}

// ---------------------------------------------------------------------------
extern "C" void kernel_launch(void* const* d_in, const int* in_sizes, int n_in,
                              void* d_out, int out_size)
{
    const float* lm   = (const float*)d_in[0];
    const float* feat = (const float*)d_in[1];
    const float* Wi   = (const float*)d_in[2];
    const float* bi   = (const float*)d_in[3];
    const float* Wj   = (const float*)d_in[4];
    const float* bj   = (const float*)d_in[5];
    const float* Wk   = (const float*)d_in[6];
    const float* bk   = (const float*)d_in[7];
    const float* Wr   = (const float*)d_in[8];
    const float* br   = (const float*)d_in[9];
    float* out = (float*)d_out;

    cudaFuncSetAttribute(proj_kernel, cudaFuncAttributeMaxDynamicSharedMemorySize, PROJ_SMEM);
    cudaFuncSetAttribute(attn_kernel, cudaFuncAttributeMaxDynamicSharedMemorySize, ATTN_SMEM);

    proj_kernel<<<dim3(NN/64, 3), 256, PROJ_SMEM>>>(lm, feat, Wi, bi, Wj, bj, Wk, bk);
    attn_kernel<<<NN/64, 256, ATTN_SMEM>>>();
    out_kernel<<<NN/32, 256>>>(feat, Wr, br, out);
}